// round 10
// baseline (speedup 1.0000x reference)
#include <cuda_runtime.h>
#include <math.h>

// ---------------- constants ----------------
#define EPSF 1e-8f
#define BC   32
#define HW   262144   // 512*512

// reversed db4 decomposition filters:
// RL[k] = DEC_LO[7-k],  RH[k] = DEC_HI[7-k] = DEC_LO[k] * (k odd ? -1 : +1)
__constant__ float c_RL[8] = {
     0.23037781330885523f,  0.7148465705525415f,   0.6308807679295904f,
    -0.02798376941698385f, -0.18703481171888114f,  0.030841381835986965f,
     0.032883011666982945f, -0.010597401784997278f };
__constant__ float c_RH[8] = {
    -0.010597401784997278f, -0.032883011666982945f, 0.030841381835986965f,
     0.18703481171888114f,  -0.02798376941698385f,  -0.6308807679295904f,
     0.7148465705525415f,   -0.23037781330885523f };
// interleaved (RL[k], RH[k]) pairs for f32x2 math, 8-byte aligned
__constant__ __align__(8) float c_Pf[16] = {
     0.23037781330885523f,  -0.010597401784997278f,
     0.7148465705525415f,   -0.032883011666982945f,
     0.6308807679295904f,    0.030841381835986965f,
    -0.02798376941698385f,   0.18703481171888114f,
    -0.18703481171888114f,  -0.02798376941698385f,
     0.030841381835986965f, -0.6308807679295904f,
     0.032883011666982945f,  0.7148465705525415f,
    -0.010597401784997278f, -0.23037781330885523f };

// level sizes: 512 -> 259 -> 133 -> 70 -> 38, padded (even) strides
#define M1 259
#define M2 133
#define M3 70
#define M4 38
#define S1 260
#define S2 134
#define S3 70
#define S4 38

__device__ __align__(16) float g_cA1[BC * M1 * S1];
__device__ __align__(16) float g_m1 [BC * M1 * S1];
__device__ __align__(16) float g_cA2[BC * M2 * S2];
__device__ __align__(16) float g_m2 [BC * M2 * S2];
__device__ __align__(16) float g_m3 [BC * M3 * S3];
__device__ __align__(16) float g_cA4[BC * M4 * S4];
__device__ __align__(16) float g_m4 [BC * M4 * S4];

// ---------------- f32x2 helpers ----------------
__device__ __forceinline__ unsigned long long bcast2(float a)
{
    unsigned long long r;
    asm("mov.b64 %0, {%1, %2};" : "=l"(r) : "f"(a), "f"(a));
    return r;
}
__device__ __forceinline__ unsigned long long fma2(unsigned long long a,
                                                   unsigned long long b,
                                                   unsigned long long c)
{
    unsigned long long d;
    asm("fma.rn.f32x2 %0, %1, %2, %3;" : "=l"(d) : "l"(a), "l"(b), "l"(c));
    return d;
}
__device__ __forceinline__ void unpk(unsigned long long v, float& a, float& b)
{
    asm("mov.b64 {%0, %1}, %2;" : "=f"(a), "=f"(b) : "l"(v));
}

// symmetric-extension index (pad(7,7,'symmetric')[...,1:]):  t = 2*out - 6 + k
__device__ __forceinline__ int eidx(int t, int N)
{
    if (t < 0)  return -1 - t;
    if (t >= N) return 2 * N - 1 - t;
    return t;
}

// ---------------- 4-row group DWT (levels 1 & 2), f32x2 packed ----------------
__device__ __forceinline__ void dwt_group4(const float* __restrict__ src,
                                           int N, int INS, int jo, int io0,
                                           float ll[4], float mg[4])
{
    const unsigned long long* cP =
        reinterpret_cast<const unsigned long long*>(c_Pf);
    unsigned long long A[4], B[4];   // A=(ll,lh)  B=(hl,hh)
    #pragma unroll
    for (int o = 0; o < 4; o++) { A[o] = 0ull; B[o] = 0ull; }

    int cb = 2 * jo - 6;
    int rb = 2 * io0 - 6;
    bool cint = (cb >= 0) && (cb + 7 < N);

    int ci[8];
    if (!cint) {
        #pragma unroll
        for (int k = 0; k < 8; k++) ci[k] = eidx(cb + k, N);
    }

    #pragma unroll
    for (int r = 0; r < 14; r++) {
        int ri = eidx(rb + r, N);
        const float* row = src + (size_t)ri * INS;
        float lo, hi;
        if (cint) {
            const float2* q = reinterpret_cast<const float2*>(row + cb);
            unsigned long long acc = 0ull;
            #pragma unroll
            for (int h = 0; h < 4; h++) {
                float2 v = q[h];
                acc = fma2(bcast2(v.x), cP[2 * h],     acc);
                acc = fma2(bcast2(v.y), cP[2 * h + 1], acc);
            }
            unpk(acc, lo, hi);
        } else {
            lo = 0.f; hi = 0.f;
            #pragma unroll
            for (int k = 0; k < 8; k++) {
                float v = row[ci[k]];
                lo = fmaf(v, c_RL[k], lo);
                hi = fmaf(v, c_RH[k], hi);
            }
        }
        unsigned long long lo2 = bcast2(lo), hi2 = bcast2(hi);
        #pragma unroll
        for (int o = 0; o < 4; o++) {
            int k = r - 2 * o;
            if (k >= 0 && k < 8) {
                A[o] = fma2(lo2, cP[k], A[o]);
                B[o] = fma2(hi2, cP[k], B[o]);
            }
        }
    }
    #pragma unroll
    for (int o = 0; o < 4; o++) {
        float l, lh, hl, hh;
        unpk(A[o], l, lh);
        unpk(B[o], hl, hh);
        ll[o] = l;
        mg[o] = sqrtf(fmaf(lh, lh, fmaf(hl, hl, fmaf(hh, hh, EPSF))));
    }
}

template<int N, int INS, int M, int OUTS>
__global__ void __launch_bounds__(256)
dwt_kernel(const float* __restrict__ in,
           float* __restrict__ outA, float* __restrict__ outM)
{
    int jo  = blockIdx.x * 32 + threadIdx.x;
    int io0 = (blockIdx.y * 8 + threadIdx.y) * 4;
    int bc  = blockIdx.z;
    if (jo >= M || io0 >= M) return;

    float ll[4], mg[4];
    dwt_group4(in + (size_t)bc * N * INS, N, INS, jo, io0, ll, mg);

    #pragma unroll
    for (int o = 0; o < 4; o++) {
        int io = io0 + o;
        if (io < M) {
            size_t off = (size_t)bc * M * OUTS + (size_t)io * OUTS + jo;
            outA[off] = ll[o];
            outM[off] = mg[o];
        }
    }
}

// ---------------- 1-row DWT (tiny levels), f32x2 packed ----------------
__device__ __forceinline__ void dwt_one(const float* __restrict__ src,
                                        int N, int rstride, int roff,
                                        int jo, int io, float& outA, float& outM)
{
    const unsigned long long* cP =
        reinterpret_cast<const unsigned long long*>(c_Pf);
    int cb = 2 * jo - 6;
    int rb = 2 * io - 6;
    bool cint = (cb >= 0) && (cb + 7 < N);
    int ci[8];
    if (!cint) {
        #pragma unroll
        for (int k = 0; k < 8; k++) ci[k] = eidx(cb + k, N);
    }
    unsigned long long A = 0ull, B = 0ull;
    #pragma unroll
    for (int r = 0; r < 8; r++) {
        int ri = eidx(rb + r, N) - roff;
        const float* row = src + (size_t)ri * rstride;
        float lo, hi;
        if (cint) {
            const float2* q = reinterpret_cast<const float2*>(row + cb);
            unsigned long long acc = 0ull;
            #pragma unroll
            for (int h = 0; h < 4; h++) {
                float2 v = q[h];
                acc = fma2(bcast2(v.x), cP[2 * h],     acc);
                acc = fma2(bcast2(v.y), cP[2 * h + 1], acc);
            }
            unpk(acc, lo, hi);
        } else {
            lo = 0.f; hi = 0.f;
            #pragma unroll
            for (int k = 0; k < 8; k++) {
                float v = row[ci[k]];
                lo = fmaf(v, c_RL[k], lo);
                hi = fmaf(v, c_RH[k], hi);
            }
        }
        A = fma2(bcast2(lo), cP[r], A);
        B = fma2(bcast2(hi), cP[r], B);
    }
    float ll, lh, hl, hh;
    unpk(A, ll, lh);
    unpk(B, hl, hh);
    outA = ll;
    outM = sqrtf(fmaf(lh, lh, fmaf(hl, hl, fmaf(hh, hh, EPSF))));
}

// ---------------- merged levels 3+4, 8 partitions per bc (256 CTAs) ----------------
__global__ void __launch_bounds__(256)
tail_kernel(const float* __restrict__ cA2,
            float* __restrict__ m3, float* __restrict__ cA4, float* __restrict__ m4)
{
    __shared__ __align__(16) float sA3[16 * 72];   // window of cA3, stride 72
    int blk = blockIdx.x;          // 0..255
    int bc  = blk >> 3;
    int p   = blk & 7;
    int t   = threadIdx.x;
    const float* src2 = cA2 + (size_t)bc * M2 * S2;

    // owned level-4 rows: [5p, min(5p+5, 38))
    int l4lo = 5 * p;
    int l4hi = min(5 * p + 5, M4);
    // cA3 rows needed: e(t) for t in [2*l4lo-6, 2*(l4hi-1)+1]
    int tmin = 2 * l4lo - 6;
    int tmax = 2 * (l4hi - 1) + 1;
    int rlo = max(0, tmin);
    int rhi = min(M3 - 1, tmax);
    if (tmin < 0)        rhi = max(rhi, -1 - tmin);
    if (tmax > M3 - 1)   rlo = min(rlo, 2 * M3 - 1 - tmax);
    // owned m3 rows: [9p, min(9p+9, 70))
    int olo = 9 * p;
    int ohi = min(9 * p + 9, M3);
    rlo = min(rlo, olo);
    rhi = max(rhi, ohi - 1);
    int nr = rhi - rlo + 1;        // <= 16 by construction

    // Phase A: compute cA3 rows [rlo, rhi], write owned m3 rows
    for (int g = t; g < nr * 70; g += 256) {
        int jo = g % 70;
        int io = rlo + g / 70;
        float ll, mg;
        dwt_one(src2, M2, S2, 0, jo, io, ll, mg);
        sA3[(io - rlo) * 72 + jo] = ll;
        if (io >= olo && io < ohi)
            m3[(size_t)bc * M3 * S3 + io * S3 + jo] = mg;
    }
    __syncthreads();

    // Phase B: level 4 on smem window
    int nout = (l4hi - l4lo) * 38;     // <= 190, single pass
    if (t < nout) {
        int jo = t % 38;
        int io = l4lo + t / 38;
        float ll, mg;
        dwt_one(sA3, M3, 72, rlo, jo, io, ll, mg);
        size_t off = (size_t)bc * M4 * S4 + io * S4 + jo;
        cA4[off] = ll;
        m4[off]  = mg;
    }
}

// ---------------- upsample coordinates (jax.image.resize 'linear') ----------------
__device__ __forceinline__ void coord(int o, int n, int& i0, int& i1, float& f)
{
    float s  = (o + 0.5f) * (n * (1.0f / 512.0f)) - 0.5f;
    float fl = floorf(s);
    f = s - fl;
    int i = (int)fl;
    i0 = i < 0 ? 0 : i;
    int j = i + 1;
    i1 = j > n - 1 ? n - 1 : j;
}

// ---------------- fused separable upsample + merge + gate ----------------
// grid (16 y-blocks, 32 bc, 4 scales), block 256.
// Stage <=18 x-upsampled source rows in smem; y-interp with warp-per-row
// uniform coordinates; gate folded into the interp weights (c0, c1).
__global__ void __launch_bounds__(256)
up_kernel(float* __restrict__ out,
          const float* __restrict__ t_emb, const float* __restrict__ gate_w)
{
    __shared__ __align__(16) float srow[18 * 512];   // 36 KB
    __shared__ float s_w;
    int ya  = blockIdx.x * 32;
    int bc  = blockIdx.y;
    int s   = blockIdx.z;
    int b   = bc >> 1, c = bc & 1;
    int tid = threadIdx.x;
    int wid = tid >> 5, lane = tid & 31;

    // gate: one warp, shuffle reduction over k=0..63
    if (tid < 32) {
        float acc = t_emb[b * 64 + tid]      * gate_w[tid * 4 + s]
                  + t_emb[b * 64 + tid + 32] * gate_w[(tid + 32) * 4 + s];
        #pragma unroll
        for (int o = 16; o; o >>= 1)
            acc += __shfl_xor_sync(0xffffffffu, acc, o);
        if (tid == 0)
            s_w = (s == 0 ? 0.5f : 1.0f) / (1.0f + expf(-acc));
    }

    int n, stride;
    const float* srcA;
    const float* srcB = 0;
    if      (s == 0) { n = M4; stride = S4; srcA = g_cA4 + (size_t)bc * M4 * S4;
                                            srcB = g_m4  + (size_t)bc * M4 * S4; }
    else if (s == 1) { n = M3; stride = S3; srcA = g_m3 + (size_t)bc * M3 * S3; }
    else if (s == 2) { n = M2; stride = S2; srcA = g_m2 + (size_t)bc * M2 * S2; }
    else             { n = M1; stride = S1; srcA = g_m1 + (size_t)bc * M1 * S1; }

    float rr = n * (1.0f / 512.0f);
    int i0a  = (int)floorf((ya + 0.5f)  * rr - 0.5f);
    int i1b  = (int)floorf((ya + 31.5f) * rr - 0.5f) + 1;
    int rloC = max(i0a, 0);
    int rhiC = min(i1b, n - 1);
    int nst  = rhiC - rloC + 1;    // <= 18

    // stage x-upsampled rows (raw, no gate)
    int xA0, xA1, xB0, xB1; float fA, fB;
    coord(tid,       n, xA0, xA1, fA);
    coord(tid + 256, n, xB0, xB1, fB);

    for (int r = 0; r < nst; r++) {
        const float* rowA = srcA + (size_t)(rloC + r) * stride;
        float a0 = rowA[xA0];
        float vA = a0 + (rowA[xA1] - a0) * fA;
        float b0 = rowA[xB0];
        float vB = b0 + (rowA[xB1] - b0) * fB;
        if (srcB) {
            const float* rowB = srcB + (size_t)(rloC + r) * stride;
            float c0 = rowB[xA0];
            vA += c0 + (rowB[xA1] - c0) * fA;
            float c1 = rowB[xB0];
            vB += c1 + (rowB[xB1] - c1) * fB;
        }
        srow[r * 512 + tid]       = vA;
        srow[r * 512 + tid + 256] = vB;
    }
    __syncthreads();

    // y-interp: warp-per-row, uniform coords, gate folded into weights
    float w = s_w;
    size_t obase = ((size_t)(b * 8 + c * 4 + s)) * HW + (size_t)ya * 512;
    #pragma unroll
    for (int j = 0; j < 4; j++) {
        int ry = wid * 4 + j;
        int y0, y1; float fy;
        coord(ya + ry, n, y0, y1, fy);
        float c1 = fy * w;
        float c0 = w - c1;
        const float4* r0 = reinterpret_cast<const float4*>(srow + (size_t)(y0 - rloC) * 512);
        const float4* r1 = reinterpret_cast<const float4*>(srow + (size_t)(y1 - rloC) * 512);
        float4* dst = reinterpret_cast<float4*>(out + obase + (size_t)ry * 512);
        #pragma unroll
        for (int it = 0; it < 4; it++) {
            int c4 = lane + it * 32;
            float4 a = r0[c4], d = r1[c4], v;
            v.x = fmaf(a.x, c0, d.x * c1);
            v.y = fmaf(a.y, c0, d.y * c1);
            v.z = fmaf(a.z, c0, d.z * c1);
            v.w = fmaf(a.w, c0, d.w * c1);
            dst[c4] = v;
        }
    }
}

// ---------------- launch ----------------
extern "C" void kernel_launch(void* const* d_in, const int* in_sizes, int n_in,
                              void* d_out, int out_size)
{
    const float* image  = (const float*)d_in[0];
    const float* t_emb  = (const float*)d_in[1];
    const float* gate_w = (const float*)d_in[2];
    float* out = (float*)d_out;

    float *cA1, *m1, *cA2, *m2, *m3, *cA4, *m4;
    cudaGetSymbolAddress((void**)&cA1, g_cA1);
    cudaGetSymbolAddress((void**)&m1,  g_m1);
    cudaGetSymbolAddress((void**)&cA2, g_cA2);
    cudaGetSymbolAddress((void**)&m2,  g_m2);
    cudaGetSymbolAddress((void**)&m3,  g_m3);
    cudaGetSymbolAddress((void**)&cA4, g_cA4);
    cudaGetSymbolAddress((void**)&m4,  g_m4);

    dim3 blk(32, 8);
    {   dim3 g((M1 + 31) / 32, (M1 + 31) / 32, BC);
        dwt_kernel<512, 512, M1, S1><<<g, blk>>>(image, cA1, m1); }
    {   dim3 g((M2 + 31) / 32, (M2 + 31) / 32, BC);
        dwt_kernel<M1, S1, M2, S2><<<g, blk>>>(cA1, cA2, m2); }

    tail_kernel<<<BC * 8, 256>>>(cA2, m3, cA4, m4);

    up_kernel<<<dim3(16, BC, 4), 256>>>(out, t_emb, gate_w);
}

// round 11
// speedup vs baseline: 1.1718x; 1.1718x over previous
#include <cuda_runtime.h>
#include <math.h>

// ---------------- constants ----------------
#define EPSF 1e-8f
#define BC   32
#define HW   262144   // 512*512

// reversed db4 decomposition filters:
// RL[k] = DEC_LO[7-k],  RH[k] = DEC_HI[7-k] = DEC_LO[k] * (k odd ? -1 : +1)
__constant__ float c_RL[8] = {
     0.23037781330885523f,  0.7148465705525415f,   0.6308807679295904f,
    -0.02798376941698385f, -0.18703481171888114f,  0.030841381835986965f,
     0.032883011666982945f, -0.010597401784997278f };
__constant__ float c_RH[8] = {
    -0.010597401784997278f, -0.032883011666982945f, 0.030841381835986965f,
     0.18703481171888114f,  -0.02798376941698385f,  -0.6308807679295904f,
     0.7148465705525415f,   -0.23037781330885523f };
// interleaved (RL[k], RH[k]) pairs for f32x2 math, 8-byte aligned
__constant__ __align__(8) float c_Pf[16] = {
     0.23037781330885523f,  -0.010597401784997278f,
     0.7148465705525415f,   -0.032883011666982945f,
     0.6308807679295904f,    0.030841381835986965f,
    -0.02798376941698385f,   0.18703481171888114f,
    -0.18703481171888114f,  -0.02798376941698385f,
     0.030841381835986965f, -0.6308807679295904f,
     0.032883011666982945f,  0.7148465705525415f,
    -0.010597401784997278f, -0.23037781330885523f };

// level sizes: 512 -> 259 -> 133 -> 70 -> 38, padded (even) strides
#define M1 259
#define M2 133
#define M3 70
#define M4 38
#define S1 260
#define S2 134
#define S3 70
#define S4 38

__device__ __align__(16) float g_cA1[BC * M1 * S1];
__device__ __align__(16) float g_m1 [BC * M1 * S1];
__device__ __align__(16) float g_cA2[BC * M2 * S2];
__device__ __align__(16) float g_m2 [BC * M2 * S2];
__device__ __align__(16) float g_m3 [BC * M3 * S3];
__device__ __align__(16) float g_cA4[BC * M4 * S4];
__device__ __align__(16) float g_m4 [BC * M4 * S4];

// ---------------- f32x2 helpers ----------------
__device__ __forceinline__ unsigned long long bcast2(float a)
{
    unsigned long long r;
    asm("mov.b64 %0, {%1, %2};" : "=l"(r) : "f"(a), "f"(a));
    return r;
}
__device__ __forceinline__ unsigned long long fma2(unsigned long long a,
                                                   unsigned long long b,
                                                   unsigned long long c)
{
    unsigned long long d;
    asm("fma.rn.f32x2 %0, %1, %2, %3;" : "=l"(d) : "l"(a), "l"(b), "l"(c));
    return d;
}
__device__ __forceinline__ void unpk(unsigned long long v, float& a, float& b)
{
    asm("mov.b64 {%0, %1}, %2;" : "=f"(a), "=f"(b) : "l"(v));
}

// symmetric-extension index (pad(7,7,'symmetric')[...,1:]):  t = 2*out - 6 + k
__device__ __forceinline__ int eidx(int t, int N)
{
    if (t < 0)  return -1 - t;
    if (t >= N) return 2 * N - 1 - t;
    return t;
}

// ---------------- 4-row group DWT (levels 1 & 2), f32x2 packed ----------------
__device__ __forceinline__ void dwt_group4(const float* __restrict__ src,
                                           int N, int INS, int jo, int io0,
                                           float ll[4], float mg[4])
{
    const unsigned long long* cP =
        reinterpret_cast<const unsigned long long*>(c_Pf);
    unsigned long long A[4], B[4];   // A=(ll,lh)  B=(hl,hh)
    #pragma unroll
    for (int o = 0; o < 4; o++) { A[o] = 0ull; B[o] = 0ull; }

    int cb = 2 * jo - 6;
    int rb = 2 * io0 - 6;
    bool cint = (cb >= 0) && (cb + 7 < N);

    int ci[8];
    if (!cint) {
        #pragma unroll
        for (int k = 0; k < 8; k++) ci[k] = eidx(cb + k, N);
    }

    #pragma unroll
    for (int r = 0; r < 14; r++) {
        int ri = eidx(rb + r, N);
        const float* row = src + (size_t)ri * INS;
        float lo, hi;
        if (cint) {
            const float2* q = reinterpret_cast<const float2*>(row + cb);
            unsigned long long acc = 0ull;
            #pragma unroll
            for (int h = 0; h < 4; h++) {
                float2 v = q[h];
                acc = fma2(bcast2(v.x), cP[2 * h],     acc);
                acc = fma2(bcast2(v.y), cP[2 * h + 1], acc);
            }
            unpk(acc, lo, hi);
        } else {
            lo = 0.f; hi = 0.f;
            #pragma unroll
            for (int k = 0; k < 8; k++) {
                float v = row[ci[k]];
                lo = fmaf(v, c_RL[k], lo);
                hi = fmaf(v, c_RH[k], hi);
            }
        }
        unsigned long long lo2 = bcast2(lo), hi2 = bcast2(hi);
        #pragma unroll
        for (int o = 0; o < 4; o++) {
            int k = r - 2 * o;
            if (k >= 0 && k < 8) {
                A[o] = fma2(lo2, cP[k], A[o]);
                B[o] = fma2(hi2, cP[k], B[o]);
            }
        }
    }
    #pragma unroll
    for (int o = 0; o < 4; o++) {
        float l, lh, hl, hh;
        unpk(A[o], l, lh);
        unpk(B[o], hl, hh);
        ll[o] = l;
        mg[o] = sqrtf(fmaf(lh, lh, fmaf(hl, hl, fmaf(hh, hh, EPSF))));
    }
}

template<int N, int INS, int M, int OUTS>
__global__ void __launch_bounds__(256)
dwt_kernel(const float* __restrict__ in,
           float* __restrict__ outA, float* __restrict__ outM)
{
    int jo  = blockIdx.x * 32 + threadIdx.x;
    int io0 = (blockIdx.y * 8 + threadIdx.y) * 4;
    int bc  = blockIdx.z;
    if (jo >= M || io0 >= M) return;

    float ll[4], mg[4];
    dwt_group4(in + (size_t)bc * N * INS, N, INS, jo, io0, ll, mg);

    #pragma unroll
    for (int o = 0; o < 4; o++) {
        int io = io0 + o;
        if (io < M) {
            size_t off = (size_t)bc * M * OUTS + (size_t)io * OUTS + jo;
            outA[off] = ll[o];
            outM[off] = mg[o];
        }
    }
}

// ---------------- 1-row DWT (tiny levels), f32x2 packed ----------------
__device__ __forceinline__ void dwt_one(const float* __restrict__ src,
                                        int N, int rstride, int roff,
                                        int jo, int io, float& outA, float& outM)
{
    const unsigned long long* cP =
        reinterpret_cast<const unsigned long long*>(c_Pf);
    int cb = 2 * jo - 6;
    int rb = 2 * io - 6;
    bool cint = (cb >= 0) && (cb + 7 < N);
    int ci[8];
    if (!cint) {
        #pragma unroll
        for (int k = 0; k < 8; k++) ci[k] = eidx(cb + k, N);
    }
    unsigned long long A = 0ull, B = 0ull;
    #pragma unroll
    for (int r = 0; r < 8; r++) {
        int ri = eidx(rb + r, N) - roff;
        const float* row = src + (size_t)ri * rstride;
        float lo, hi;
        if (cint) {
            const float2* q = reinterpret_cast<const float2*>(row + cb);
            unsigned long long acc = 0ull;
            #pragma unroll
            for (int h = 0; h < 4; h++) {
                float2 v = q[h];
                acc = fma2(bcast2(v.x), cP[2 * h],     acc);
                acc = fma2(bcast2(v.y), cP[2 * h + 1], acc);
            }
            unpk(acc, lo, hi);
        } else {
            lo = 0.f; hi = 0.f;
            #pragma unroll
            for (int k = 0; k < 8; k++) {
                float v = row[ci[k]];
                lo = fmaf(v, c_RL[k], lo);
                hi = fmaf(v, c_RH[k], hi);
            }
        }
        A = fma2(bcast2(lo), cP[r], A);
        B = fma2(bcast2(hi), cP[r], B);
    }
    float ll, lh, hl, hh;
    unpk(A, ll, lh);
    unpk(B, hl, hh);
    outA = ll;
    outM = sqrtf(fmaf(lh, lh, fmaf(hl, hl, fmaf(hh, hh, EPSF))));
}

// ---------------- merged levels 3+4, 8 partitions per bc (256 CTAs) ----------------
__global__ void __launch_bounds__(256)
tail_kernel(const float* __restrict__ cA2,
            float* __restrict__ m3, float* __restrict__ cA4, float* __restrict__ m4)
{
    __shared__ __align__(16) float sA3[16 * 72];   // window of cA3, stride 72
    int blk = blockIdx.x;          // 0..255
    int bc  = blk >> 3;
    int p   = blk & 7;
    int t   = threadIdx.x;
    const float* src2 = cA2 + (size_t)bc * M2 * S2;

    // owned level-4 rows: [5p, min(5p+5, 38))
    int l4lo = 5 * p;
    int l4hi = min(5 * p + 5, M4);
    // cA3 rows needed: e(t) for t in [2*l4lo-6, 2*(l4hi-1)+1]
    int tmin = 2 * l4lo - 6;
    int tmax = 2 * (l4hi - 1) + 1;
    int rlo = max(0, tmin);
    int rhi = min(M3 - 1, tmax);
    if (tmin < 0)        rhi = max(rhi, -1 - tmin);
    if (tmax > M3 - 1)   rlo = min(rlo, 2 * M3 - 1 - tmax);
    // owned m3 rows: [9p, min(9p+9, 70))
    int olo = 9 * p;
    int ohi = min(9 * p + 9, M3);
    rlo = min(rlo, olo);
    rhi = max(rhi, ohi - 1);
    int nr = rhi - rlo + 1;        // <= 16 by construction

    // Phase A: compute cA3 rows [rlo, rhi], write owned m3 rows
    for (int g = t; g < nr * 70; g += 256) {
        int jo = g % 70;
        int io = rlo + g / 70;
        float ll, mg;
        dwt_one(src2, M2, S2, 0, jo, io, ll, mg);
        sA3[(io - rlo) * 72 + jo] = ll;
        if (io >= olo && io < ohi)
            m3[(size_t)bc * M3 * S3 + io * S3 + jo] = mg;
    }
    __syncthreads();

    // Phase B: level 4 on smem window
    int nout = (l4hi - l4lo) * 38;     // <= 190, single pass
    if (t < nout) {
        int jo = t % 38;
        int io = l4lo + t / 38;
        float ll, mg;
        dwt_one(sA3, M3, 72, rlo, jo, io, ll, mg);
        size_t off = (size_t)bc * M4 * S4 + io * S4 + jo;
        cA4[off] = ll;
        m4[off]  = mg;
    }
}

// ---------------- upsample coordinates (jax.image.resize 'linear') ----------------
__device__ __forceinline__ void coord(int o, int n, int& i0, int& i1, float& f)
{
    float s  = (o + 0.5f) * (n * (1.0f / 512.0f)) - 0.5f;
    float fl = floorf(s);
    f = s - fl;
    int i = (int)fl;
    i0 = i < 0 ? 0 : i;
    int j = i + 1;
    i1 = j > n - 1 ? n - 1 : j;
}

// ---------------- fused separable upsample + merge + gate ----------------
// grid (32 y-blocks of 16 rows, 32 bc, 4 scales) = 4096 CTAs, block 256.
// Stage <=10 x-upsampled source rows in smem (22 KB -> 8 CTAs/SM);
// y-interp warp-per-row with uniform coords; gate folded into weights;
// streaming stores (output is write-once).
__global__ void __launch_bounds__(256)
up_kernel(float* __restrict__ out,
          const float* __restrict__ t_emb, const float* __restrict__ gate_w)
{
    __shared__ __align__(16) float srow[11 * 512];   // 22 KB
    __shared__ float s_w;
    int ya  = blockIdx.x * 16;
    int bc  = blockIdx.y;
    int s   = blockIdx.z;
    int b   = bc >> 1, c = bc & 1;
    int tid = threadIdx.x;
    int wid = tid >> 5, lane = tid & 31;

    // gate: one warp, shuffle reduction over k=0..63
    if (tid < 32) {
        float acc = t_emb[b * 64 + tid]      * gate_w[tid * 4 + s]
                  + t_emb[b * 64 + tid + 32] * gate_w[(tid + 32) * 4 + s];
        #pragma unroll
        for (int o = 16; o; o >>= 1)
            acc += __shfl_xor_sync(0xffffffffu, acc, o);
        if (tid == 0)
            s_w = (s == 0 ? 0.5f : 1.0f) / (1.0f + expf(-acc));
    }

    int n, stride;
    const float* srcA;
    const float* srcB = 0;
    if      (s == 0) { n = M4; stride = S4; srcA = g_cA4 + (size_t)bc * M4 * S4;
                                            srcB = g_m4  + (size_t)bc * M4 * S4; }
    else if (s == 1) { n = M3; stride = S3; srcA = g_m3 + (size_t)bc * M3 * S3; }
    else if (s == 2) { n = M2; stride = S2; srcA = g_m2 + (size_t)bc * M2 * S2; }
    else             { n = M1; stride = S1; srcA = g_m1 + (size_t)bc * M1 * S1; }

    float rr = n * (1.0f / 512.0f);
    int i0a  = (int)floorf((ya + 0.5f)  * rr - 0.5f);
    int i1b  = (int)floorf((ya + 15.5f) * rr - 0.5f) + 1;
    int rloC = max(i0a, 0);
    int rhiC = min(i1b, n - 1);
    int nst  = rhiC - rloC + 1;    // <= 10

    // stage x-upsampled rows (raw, no gate)
    int xA0, xA1, xB0, xB1; float fA, fB;
    coord(tid,       n, xA0, xA1, fA);
    coord(tid + 256, n, xB0, xB1, fB);

    for (int r = 0; r < nst; r++) {
        const float* rowA = srcA + (size_t)(rloC + r) * stride;
        float a0 = rowA[xA0];
        float vA = a0 + (rowA[xA1] - a0) * fA;
        float b0 = rowA[xB0];
        float vB = b0 + (rowA[xB1] - b0) * fB;
        if (srcB) {
            const float* rowB = srcB + (size_t)(rloC + r) * stride;
            float c0 = rowB[xA0];
            vA += c0 + (rowB[xA1] - c0) * fA;
            float c1 = rowB[xB0];
            vB += c1 + (rowB[xB1] - c1) * fB;
        }
        srow[r * 512 + tid]       = vA;
        srow[r * 512 + tid + 256] = vB;
    }
    __syncthreads();

    // y-interp: warp-per-row (2 rows per warp), uniform coords, gate in weights
    float w = s_w;
    size_t obase = ((size_t)(b * 8 + c * 4 + s)) * HW + (size_t)ya * 512;
    #pragma unroll
    for (int j = 0; j < 2; j++) {
        int ry = wid * 2 + j;
        int y0, y1; float fy;
        coord(ya + ry, n, y0, y1, fy);
        float c1 = fy * w;
        float c0 = w - c1;
        const float4* r0 = reinterpret_cast<const float4*>(srow + (size_t)(y0 - rloC) * 512);
        const float4* r1 = reinterpret_cast<const float4*>(srow + (size_t)(y1 - rloC) * 512);
        float4* dst = reinterpret_cast<float4*>(out + obase + (size_t)ry * 512);
        #pragma unroll
        for (int it = 0; it < 4; it++) {
            int c4 = lane + it * 32;
            float4 a = r0[c4], d = r1[c4], v;
            v.x = fmaf(a.x, c0, d.x * c1);
            v.y = fmaf(a.y, c0, d.y * c1);
            v.z = fmaf(a.z, c0, d.z * c1);
            v.w = fmaf(a.w, c0, d.w * c1);
            __stcs(dst + c4, v);
        }
    }
}

// ---------------- launch ----------------
extern "C" void kernel_launch(void* const* d_in, const int* in_sizes, int n_in,
                              void* d_out, int out_size)
{
    const float* image  = (const float*)d_in[0];
    const float* t_emb  = (const float*)d_in[1];
    const float* gate_w = (const float*)d_in[2];
    float* out = (float*)d_out;

    float *cA1, *m1, *cA2, *m2, *m3, *cA4, *m4;
    cudaGetSymbolAddress((void**)&cA1, g_cA1);
    cudaGetSymbolAddress((void**)&m1,  g_m1);
    cudaGetSymbolAddress((void**)&cA2, g_cA2);
    cudaGetSymbolAddress((void**)&m2,  g_m2);
    cudaGetSymbolAddress((void**)&m3,  g_m3);
    cudaGetSymbolAddress((void**)&cA4, g_cA4);
    cudaGetSymbolAddress((void**)&m4,  g_m4);

    dim3 blk(32, 8);
    {   dim3 g((M1 + 31) / 32, (M1 + 31) / 32, BC);
        dwt_kernel<512, 512, M1, S1><<<g, blk>>>(image, cA1, m1); }
    {   dim3 g((M2 + 31) / 32, (M2 + 31) / 32, BC);
        dwt_kernel<M1, S1, M2, S2><<<g, blk>>>(cA1, cA2, m2); }

    tail_kernel<<<BC * 8, 256>>>(cA2, m3, cA4, m4);

    up_kernel<<<dim3(32, BC, 4), 256>>>(out, t_emb, gate_w);
}

// round 14
// speedup vs baseline: 1.2380x; 1.0565x over previous
#include <cuda_runtime.h>
#include <math.h>

// ---------------- constants ----------------
#define EPSF 1e-8f
#define BC   32
#define HW   262144   // 512*512

// reversed db4 decomposition filters:
// RL[k] = DEC_LO[7-k],  RH[k] = DEC_HI[7-k] = DEC_LO[k] * (k odd ? -1 : +1)
__constant__ float c_RL[8] = {
     0.23037781330885523f,  0.7148465705525415f,   0.6308807679295904f,
    -0.02798376941698385f, -0.18703481171888114f,  0.030841381835986965f,
     0.032883011666982945f, -0.010597401784997278f };
__constant__ float c_RH[8] = {
    -0.010597401784997278f, -0.032883011666982945f, 0.030841381835986965f,
     0.18703481171888114f,  -0.02798376941698385f,  -0.6308807679295904f,
     0.7148465705525415f,   -0.23037781330885523f };
// interleaved (RL[k], RH[k]) pairs for f32x2 math, 8-byte aligned
__constant__ __align__(8) float c_Pf[16] = {
     0.23037781330885523f,  -0.010597401784997278f,
     0.7148465705525415f,   -0.032883011666982945f,
     0.6308807679295904f,    0.030841381835986965f,
    -0.02798376941698385f,   0.18703481171888114f,
    -0.18703481171888114f,  -0.02798376941698385f,
     0.030841381835986965f, -0.6308807679295904f,
     0.032883011666982945f,  0.7148465705525415f,
    -0.010597401784997278f, -0.23037781330885523f };

// level sizes: 512 -> 259 -> 133 -> 70 -> 38, padded (even) strides
#define M1 259
#define M2 133
#define M3 70
#define M4 38
#define S1 260
#define S2 134
#define S3 70
#define S4 38

__device__ __align__(16) float g_cA1[BC * M1 * S1];
__device__ __align__(16) float g_m1 [BC * M1 * S1];
__device__ __align__(16) float g_cA2[BC * M2 * S2];
__device__ __align__(16) float g_m2 [BC * M2 * S2];
__device__ __align__(16) float g_m3 [BC * M3 * S3];
__device__ __align__(16) float g_cA4[BC * M4 * S4];
__device__ __align__(16) float g_m4 [BC * M4 * S4];

// ---------------- f32x2 helpers ----------------
__device__ __forceinline__ unsigned long long bcast2(float a)
{
    unsigned long long r;
    asm("mov.b64 %0, {%1, %2};" : "=l"(r) : "f"(a), "f"(a));
    return r;
}
__device__ __forceinline__ unsigned long long fma2(unsigned long long a,
                                                   unsigned long long b,
                                                   unsigned long long c)
{
    unsigned long long d;
    asm("fma.rn.f32x2 %0, %1, %2, %3;" : "=l"(d) : "l"(a), "l"(b), "l"(c));
    return d;
}
__device__ __forceinline__ void unpk(unsigned long long v, float& a, float& b)
{
    asm("mov.b64 {%0, %1}, %2;" : "=f"(a), "=f"(b) : "l"(v));
}

// symmetric-extension index (pad(7,7,'symmetric')[...,1:]):  t = 2*out - 6 + k
__device__ __forceinline__ int eidx(int t, int N)
{
    if (t < 0)  return -1 - t;
    if (t >= N) return 2 * N - 1 - t;
    return t;
}
// staging variant with safety clamp (for edge tiles that extend past 2N-1)
__device__ __forceinline__ int eclamp(int t, int N)
{
    if (t < 0)       t = -1 - t;
    else if (t >= N) t = 2 * N - 1 - t;
    return max(0, min(t, N - 1));
}

// ---------------- tiled separable DWT (levels 1 & 2) ----------------
// One CTA = 32x32 output tile. Stage 70x70 input window in smem,
// horizontal db4 pass to (lo,hi) pairs in smem, vertical pass in registers.
template<int N, int INS, int M, int OUTS>
__global__ void __launch_bounds__(256)
dwt_tile_kernel(const float* __restrict__ in,
                float* __restrict__ outA, float* __restrict__ outM)
{
    __shared__ __align__(16) float  sIn[70 * 72];    // 20.2 KB, stride 72 (even)
    __shared__ __align__(16) float2 sLH[70 * 32];    // 17.9 KB
    const unsigned long long* cP =
        reinterpret_cast<const unsigned long long*>(c_Pf);

    int jo0 = blockIdx.x * 32;
    int io0 = blockIdx.y * 32;
    int bc  = blockIdx.z;
    int tx  = threadIdx.x;          // 0..31  (output col within tile)
    int ty  = threadIdx.y;          // 0..7
    int tid = ty * 32 + tx;

    const float* src = in + (size_t)bc * N * INS;
    int cb0 = 2 * jo0 - 6;
    int rb0 = 2 * io0 - 6;

    // ---- stage input window (one global read per element) ----
    #pragma unroll 5
    for (int idx = tid; idx < 70 * 70; idx += 256) {
        int r = idx / 70;
        int c = idx - r * 70;
        int gr = eclamp(rb0 + r, N);
        int gc = eclamp(cb0 + c, N);
        sIn[r * 72 + c] = __ldg(src + (size_t)gr * INS + gc);
    }
    __syncthreads();

    // ---- horizontal pass: (lo,hi) for rows 0..69, cols tx ----
    for (int r = ty; r < 70; r += 8) {
        const float2* q = reinterpret_cast<const float2*>(sIn + r * 72 + 2 * tx);
        unsigned long long acc = 0ull;
        #pragma unroll
        for (int h = 0; h < 4; h++) {
            float2 v = q[h];
            acc = fma2(bcast2(v.x), cP[2 * h],     acc);
            acc = fma2(bcast2(v.y), cP[2 * h + 1], acc);
        }
        float lo, hi;
        unpk(acc, lo, hi);
        sLH[r * 32 + tx] = make_float2(lo, hi);
    }
    __syncthreads();

    // ---- vertical pass: 4 output rows per thread (ti = 4*ty + o) ----
    unsigned long long A[4], B[4];   // A=(ll,lh)  B=(hl,hh)
    #pragma unroll
    for (int o = 0; o < 4; o++) { A[o] = 0ull; B[o] = 0ull; }

    #pragma unroll
    for (int d = 0; d < 14; d++) {
        float2 p = sLH[(8 * ty + d) * 32 + tx];
        unsigned long long lo2 = bcast2(p.x), hi2 = bcast2(p.y);
        #pragma unroll
        for (int o = 0; o < 4; o++) {
            int k = d - 2 * o;
            if (k >= 0 && k < 8) {
                A[o] = fma2(lo2, cP[k], A[o]);
                B[o] = fma2(hi2, cP[k], B[o]);
            }
        }
    }

    int jo = jo0 + tx;
    if (jo < M) {
        #pragma unroll
        for (int o = 0; o < 4; o++) {
            int io = io0 + 4 * ty + o;
            if (io < M) {
                float ll, lh, hl, hh;
                unpk(A[o], ll, lh);
                unpk(B[o], hl, hh);
                size_t off = (size_t)bc * M * OUTS + (size_t)io * OUTS + jo;
                outA[off] = ll;
                outM[off] = sqrtf(fmaf(lh, lh, fmaf(hl, hl, fmaf(hh, hh, EPSF))));
            }
        }
    }
}

// ---------------- 1-row DWT (tiny levels), f32x2 packed ----------------
__device__ __forceinline__ void dwt_one(const float* __restrict__ src,
                                        int N, int rstride, int roff,
                                        int jo, int io, float& outA, float& outM)
{
    const unsigned long long* cP =
        reinterpret_cast<const unsigned long long*>(c_Pf);
    int cb = 2 * jo - 6;
    int rb = 2 * io - 6;
    bool cint = (cb >= 0) && (cb + 7 < N);
    int ci[8];
    if (!cint) {
        #pragma unroll
        for (int k = 0; k < 8; k++) ci[k] = eidx(cb + k, N);
    }
    unsigned long long A = 0ull, B = 0ull;
    #pragma unroll
    for (int r = 0; r < 8; r++) {
        int ri = eidx(rb + r, N) - roff;
        const float* row = src + (size_t)ri * rstride;
        float lo, hi;
        if (cint) {
            const float2* q = reinterpret_cast<const float2*>(row + cb);
            unsigned long long acc = 0ull;
            #pragma unroll
            for (int h = 0; h < 4; h++) {
                float2 v = q[h];
                acc = fma2(bcast2(v.x), cP[2 * h],     acc);
                acc = fma2(bcast2(v.y), cP[2 * h + 1], acc);
            }
            unpk(acc, lo, hi);
        } else {
            lo = 0.f; hi = 0.f;
            #pragma unroll
            for (int k = 0; k < 8; k++) {
                float v = row[ci[k]];
                lo = fmaf(v, c_RL[k], lo);
                hi = fmaf(v, c_RH[k], hi);
            }
        }
        A = fma2(bcast2(lo), cP[r], A);
        B = fma2(bcast2(hi), cP[r], B);
    }
    float ll, lh, hl, hh;
    unpk(A, ll, lh);
    unpk(B, hl, hh);
    outA = ll;
    outM = sqrtf(fmaf(lh, lh, fmaf(hl, hl, fmaf(hh, hh, EPSF))));
}

// ---------------- merged levels 3+4, 8 partitions per bc (256 CTAs) ----------------
__global__ void __launch_bounds__(256)
tail_kernel(const float* __restrict__ cA2,
            float* __restrict__ m3, float* __restrict__ cA4, float* __restrict__ m4)
{
    __shared__ __align__(16) float sA3[16 * 72];   // window of cA3, stride 72
    int blk = blockIdx.x;          // 0..255
    int bc  = blk >> 3;
    int p   = blk & 7;
    int t   = threadIdx.x;
    const float* src2 = cA2 + (size_t)bc * M2 * S2;

    // owned level-4 rows: [5p, min(5p+5, 38))
    int l4lo = 5 * p;
    int l4hi = min(5 * p + 5, M4);
    // cA3 rows needed: e(t) for t in [2*l4lo-6, 2*(l4hi-1)+1]
    int tmin = 2 * l4lo - 6;
    int tmax = 2 * (l4hi - 1) + 1;
    int rlo = max(0, tmin);
    int rhi = min(M3 - 1, tmax);
    if (tmin < 0)        rhi = max(rhi, -1 - tmin);
    if (tmax > M3 - 1)   rlo = min(rlo, 2 * M3 - 1 - tmax);
    // owned m3 rows: [9p, min(9p+9, 70))
    int olo = 9 * p;
    int ohi = min(9 * p + 9, M3);
    rlo = min(rlo, olo);
    rhi = max(rhi, ohi - 1);
    int nr = rhi - rlo + 1;        // <= 16 by construction

    // Phase A: compute cA3 rows [rlo, rhi], write owned m3 rows
    for (int g = t; g < nr * 70; g += 256) {
        int jo = g % 70;
        int io = rlo + g / 70;
        float ll, mg;
        dwt_one(src2, M2, S2, 0, jo, io, ll, mg);
        sA3[(io - rlo) * 72 + jo] = ll;
        if (io >= olo && io < ohi)
            m3[(size_t)bc * M3 * S3 + io * S3 + jo] = mg;
    }
    __syncthreads();

    // Phase B: level 4 on smem window
    int nout = (l4hi - l4lo) * 38;     // <= 190, single pass
    if (t < nout) {
        int jo = t % 38;
        int io = l4lo + t / 38;
        float ll, mg;
        dwt_one(sA3, M3, 72, rlo, jo, io, ll, mg);
        size_t off = (size_t)bc * M4 * S4 + io * S4 + jo;
        cA4[off] = ll;
        m4[off]  = mg;
    }
}

// ---------------- upsample coordinates (jax.image.resize 'linear') ----------------
__device__ __forceinline__ void coord(int o, int n, int& i0, int& i1, float& f)
{
    float s  = (o + 0.5f) * (n * (1.0f / 512.0f)) - 0.5f;
    float fl = floorf(s);
    f = s - fl;
    int i = (int)fl;
    i0 = i < 0 ? 0 : i;
    int j = i + 1;
    i1 = j > n - 1 ? n - 1 : j;
}

// ---------------- fused separable upsample + merge + gate ----------------
// grid (32 y-blocks of 16 rows, 32 bc, 4 scales) = 4096 CTAs, block 256.
// Stage <=10 x-upsampled source rows in smem (22 KB -> 8 CTAs/SM);
// y-interp warp-per-row with uniform coords; gate folded into weights;
// streaming stores (output is write-once).
__global__ void __launch_bounds__(256)
up_kernel(float* __restrict__ out,
          const float* __restrict__ t_emb, const float* __restrict__ gate_w)
{
    __shared__ __align__(16) float srow[11 * 512];   // 22 KB
    __shared__ float s_w;
    int ya  = blockIdx.x * 16;
    int bc  = blockIdx.y;
    int s   = blockIdx.z;
    int b   = bc >> 1, c = bc & 1;
    int tid = threadIdx.x;
    int wid = tid >> 5, lane = tid & 31;

    // gate: one warp, shuffle reduction over k=0..63
    if (tid < 32) {
        float acc = t_emb[b * 64 + tid]      * gate_w[tid * 4 + s]
                  + t_emb[b * 64 + tid + 32] * gate_w[(tid + 32) * 4 + s];
        #pragma unroll
        for (int o = 16; o; o >>= 1)
            acc += __shfl_xor_sync(0xffffffffu, acc, o);
        if (tid == 0)
            s_w = (s == 0 ? 0.5f : 1.0f) / (1.0f + expf(-acc));
    }

    int n, stride;
    const float* srcA;
    const float* srcB = 0;
    if      (s == 0) { n = M4; stride = S4; srcA = g_cA4 + (size_t)bc * M4 * S4;
                                            srcB = g_m4  + (size_t)bc * M4 * S4; }
    else if (s == 1) { n = M3; stride = S3; srcA = g_m3 + (size_t)bc * M3 * S3; }
    else if (s == 2) { n = M2; stride = S2; srcA = g_m2 + (size_t)bc * M2 * S2; }
    else             { n = M1; stride = S1; srcA = g_m1 + (size_t)bc * M1 * S1; }

    float rr = n * (1.0f / 512.0f);
    int i0a  = (int)floorf((ya + 0.5f)  * rr - 0.5f);
    int i1b  = (int)floorf((ya + 15.5f) * rr - 0.5f) + 1;
    int rloC = max(i0a, 0);
    int rhiC = min(i1b, n - 1);
    int nst  = rhiC - rloC + 1;    // <= 10

    // stage x-upsampled rows (raw, no gate)
    int xA0, xA1, xB0, xB1; float fA, fB;
    coord(tid,       n, xA0, xA1, fA);
    coord(tid + 256, n, xB0, xB1, fB);

    for (int r = 0; r < nst; r++) {
        const float* rowA = srcA + (size_t)(rloC + r) * stride;
        float a0 = rowA[xA0];
        float vA = a0 + (rowA[xA1] - a0) * fA;
        float b0 = rowA[xB0];
        float vB = b0 + (rowA[xB1] - b0) * fB;
        if (srcB) {
            const float* rowB = srcB + (size_t)(rloC + r) * stride;
            float c0 = rowB[xA0];
            vA += c0 + (rowB[xA1] - c0) * fA;
            float c1 = rowB[xB0];
            vB += c1 + (rowB[xB1] - c1) * fB;
        }
        srow[r * 512 + tid]       = vA;
        srow[r * 512 + tid + 256] = vB;
    }
    __syncthreads();

    // y-interp: warp-per-row (2 rows per warp), uniform coords, gate in weights
    float w = s_w;
    size_t obase = ((size_t)(b * 8 + c * 4 + s)) * HW + (size_t)ya * 512;
    #pragma unroll
    for (int j = 0; j < 2; j++) {
        int ry = wid * 2 + j;
        int y0, y1; float fy;
        coord(ya + ry, n, y0, y1, fy);
        float c1 = fy * w;
        float c0 = w - c1;
        const float4* r0 = reinterpret_cast<const float4*>(srow + (size_t)(y0 - rloC) * 512);
        const float4* r1 = reinterpret_cast<const float4*>(srow + (size_t)(y1 - rloC) * 512);
        float4* dst = reinterpret_cast<float4*>(out + obase + (size_t)ry * 512);
        #pragma unroll
        for (int it = 0; it < 4; it++) {
            int c4 = lane + it * 32;
            float4 a = r0[c4], d = r1[c4], v;
            v.x = fmaf(a.x, c0, d.x * c1);
            v.y = fmaf(a.y, c0, d.y * c1);
            v.z = fmaf(a.z, c0, d.z * c1);
            v.w = fmaf(a.w, c0, d.w * c1);
            __stcs(dst + c4, v);
        }
    }
}

// ---------------- launch ----------------
extern "C" void kernel_launch(void* const* d_in, const int* in_sizes, int n_in,
                              void* d_out, int out_size)
{
    const float* image  = (const float*)d_in[0];
    const float* t_emb  = (const float*)d_in[1];
    const float* gate_w = (const float*)d_in[2];
    float* out = (float*)d_out;

    float *cA1, *m1, *cA2, *m2, *m3, *cA4, *m4;
    cudaGetSymbolAddress((void**)&cA1, g_cA1);
    cudaGetSymbolAddress((void**)&m1,  g_m1);
    cudaGetSymbolAddress((void**)&cA2, g_cA2);
    cudaGetSymbolAddress((void**)&m2,  g_m2);
    cudaGetSymbolAddress((void**)&m3,  g_m3);
    cudaGetSymbolAddress((void**)&cA4, g_cA4);
    cudaGetSymbolAddress((void**)&m4,  g_m4);

    dim3 blk(32, 8);
    {   dim3 g((M1 + 31) / 32, (M1 + 31) / 32, BC);   // 9 x 9 x 32
        dwt_tile_kernel<512, 512, M1, S1><<<g, blk>>>(image, cA1, m1); }
    {   dim3 g((M2 + 31) / 32, (M2 + 31) / 32, BC);   // 5 x 5 x 32
        dwt_tile_kernel<M1, S1, M2, S2><<<g, blk>>>(cA1, cA2, m2); }

    tail_kernel<<<BC * 8, 256>>>(cA2, m3, cA4, m4);

    up_kernel<<<dim3(32, BC, 4), 256>>>(out, t_emb, gate_w);
}

// round 15
// speedup vs baseline: 1.2779x; 1.0322x over previous
#include <cuda_runtime.h>
#include <math.h>

// ---------------- constants ----------------
#define EPSF 1e-8f
#define BC   32
#define HW   262144   // 512*512

// reversed db4 decomposition filters:
// RL[k] = DEC_LO[7-k],  RH[k] = DEC_HI[7-k] = DEC_LO[k] * (k odd ? -1 : +1)
__constant__ float c_RL[8] = {
     0.23037781330885523f,  0.7148465705525415f,   0.6308807679295904f,
    -0.02798376941698385f, -0.18703481171888114f,  0.030841381835986965f,
     0.032883011666982945f, -0.010597401784997278f };
__constant__ float c_RH[8] = {
    -0.010597401784997278f, -0.032883011666982945f, 0.030841381835986965f,
     0.18703481171888114f,  -0.02798376941698385f,  -0.6308807679295904f,
     0.7148465705525415f,   -0.23037781330885523f };
// interleaved (RL[k], RH[k]) pairs for f32x2 math, 8-byte aligned
__constant__ __align__(8) float c_Pf[16] = {
     0.23037781330885523f,  -0.010597401784997278f,
     0.7148465705525415f,   -0.032883011666982945f,
     0.6308807679295904f,    0.030841381835986965f,
    -0.02798376941698385f,   0.18703481171888114f,
    -0.18703481171888114f,  -0.02798376941698385f,
     0.030841381835986965f, -0.6308807679295904f,
     0.032883011666982945f,  0.7148465705525415f,
    -0.010597401784997278f, -0.23037781330885523f };

// level sizes: 512 -> 259 -> 133 -> 70 -> 38, padded (even) strides
#define M1 259
#define M2 133
#define M3 70
#define M4 38
#define S1 260
#define S2 134
#define S3 70
#define S4 38

__device__ __align__(16) float g_cA1[BC * M1 * S1];
__device__ __align__(16) float g_m1 [BC * M1 * S1];
__device__ __align__(16) float g_cA2[BC * M2 * S2];
__device__ __align__(16) float g_m2 [BC * M2 * S2];
__device__ __align__(16) float g_m3 [BC * M3 * S3];
__device__ __align__(16) float g_cA4[BC * M4 * S4];
__device__ __align__(16) float g_m4 [BC * M4 * S4];

// ---------------- f32x2 helpers ----------------
__device__ __forceinline__ unsigned long long bcast2(float a)
{
    unsigned long long r;
    asm("mov.b64 %0, {%1, %2};" : "=l"(r) : "f"(a), "f"(a));
    return r;
}
__device__ __forceinline__ unsigned long long fma2(unsigned long long a,
                                                   unsigned long long b,
                                                   unsigned long long c)
{
    unsigned long long d;
    asm("fma.rn.f32x2 %0, %1, %2, %3;" : "=l"(d) : "l"(a), "l"(b), "l"(c));
    return d;
}
__device__ __forceinline__ unsigned long long mul2(unsigned long long a,
                                                   unsigned long long b)
{
    unsigned long long d;
    asm("mul.rn.f32x2 %0, %1, %2;" : "=l"(d) : "l"(a), "l"(b));
    return d;
}
__device__ __forceinline__ void unpk(unsigned long long v, float& a, float& b)
{
    asm("mov.b64 {%0, %1}, %2;" : "=f"(a), "=f"(b) : "l"(v));
}
__device__ __forceinline__ void st2_cs(void* p, unsigned long long v0,
                                       unsigned long long v1)
{
    asm volatile("st.global.cs.v2.u64 [%0], {%1, %2};"
                 :: "l"(p), "l"(v0), "l"(v1) : "memory");
}

// symmetric-extension index (pad(7,7,'symmetric')[...,1:]):  t = 2*out - 6 + k
__device__ __forceinline__ int eidx(int t, int N)
{
    if (t < 0)  return -1 - t;
    if (t >= N) return 2 * N - 1 - t;
    return t;
}
// staging variant with safety clamp (for edge tiles that extend past 2N-1)
__device__ __forceinline__ int eclamp(int t, int N)
{
    if (t < 0)       t = -1 - t;
    else if (t >= N) t = 2 * N - 1 - t;
    return max(0, min(t, N - 1));
}

// ---------------- tiled separable DWT (levels 1 & 2) ----------------
// One CTA = 32x32 output tile. Stage 70x70 input window in smem; the
// horizontal pass overwrites cols [0,64) of each row with packed (lo,hi)
// u64 pairs (safe: per-row, per-warp, loads precede the dependent store).
template<int N, int INS, int M, int OUTS>
__global__ void __launch_bounds__(256, 6)
dwt_tile_kernel(const float* __restrict__ in,
                float* __restrict__ outA, float* __restrict__ outM)
{
    __shared__ __align__(16) float sIn[70 * 72];    // 20.3 KB, stride 72 (even)
    const unsigned long long* cP =
        reinterpret_cast<const unsigned long long*>(c_Pf);

    int jo0 = blockIdx.x * 32;
    int io0 = blockIdx.y * 32;
    int bc  = blockIdx.z;
    int tx  = threadIdx.x;          // 0..31
    int ty  = threadIdx.y;          // 0..7

    const float* src = in + (size_t)bc * N * INS;
    int cb0 = 2 * jo0 - 6;
    int rb0 = 2 * io0 - 6;

    bool winter = (cb0 >= 0) && (cb0 + 69 < N) && (rb0 >= 0) && (rb0 + 69 < N);

    // ---- stage input window (coalesced, division-free) ----
    if (winter) {
        const float* base = src + (size_t)rb0 * INS + cb0;
        #pragma unroll
        for (int rr = 0; rr < 9; rr++) {
            int r = rr * 8 + ty;
            if (r < 70) {
                const float* p = base + (size_t)r * INS;
                sIn[r * 72 + tx]      = __ldg(p + tx);
                sIn[r * 72 + tx + 32] = __ldg(p + tx + 32);
                if (tx < 6)
                    sIn[r * 72 + tx + 64] = __ldg(p + tx + 64);
            }
        }
    } else {
        int gcA = eclamp(cb0 + tx,      N);
        int gcB = eclamp(cb0 + tx + 32, N);
        int gcC = eclamp(cb0 + tx + 64, N);
        #pragma unroll
        for (int rr = 0; rr < 9; rr++) {
            int r = rr * 8 + ty;
            if (r < 70) {
                const float* p = src + (size_t)eclamp(rb0 + r, N) * INS;
                sIn[r * 72 + tx]      = __ldg(p + gcA);
                sIn[r * 72 + tx + 32] = __ldg(p + gcB);
                if (tx < 6)
                    sIn[r * 72 + tx + 64] = __ldg(p + gcC);
            }
        }
    }
    __syncthreads();

    // ---- horizontal pass: row r -> packed (lo,hi) u64 in cols [0,64) ----
    #pragma unroll
    for (int rr = 0; rr < 9; rr++) {
        int r = rr * 8 + ty;
        if (r < 70) {
            const float2* q = reinterpret_cast<const float2*>(sIn + r * 72) + tx;
            unsigned long long acc = 0ull;
            #pragma unroll
            for (int h = 0; h < 4; h++) {
                float2 v = q[h];
                acc = fma2(bcast2(v.x), cP[2 * h],     acc);
                acc = fma2(bcast2(v.y), cP[2 * h + 1], acc);
            }
            reinterpret_cast<unsigned long long*>(sIn + r * 72)[tx] = acc;
        }
    }
    __syncthreads();

    // ---- vertical pass: 4 output rows per thread ----
    unsigned long long A[4], B[4];   // A=(ll,lh)  B=(hl,hh)
    #pragma unroll
    for (int o = 0; o < 4; o++) { A[o] = 0ull; B[o] = 0ull; }

    #pragma unroll
    for (int d = 0; d < 14; d++) {
        unsigned long long p =
            reinterpret_cast<const unsigned long long*>(sIn + (8 * ty + d) * 72)[tx];
        float lo, hi;
        unpk(p, lo, hi);
        unsigned long long lo2 = bcast2(lo), hi2 = bcast2(hi);
        #pragma unroll
        for (int o = 0; o < 4; o++) {
            int k = d - 2 * o;
            if (k >= 0 && k < 8) {
                A[o] = fma2(lo2, cP[k], A[o]);
                B[o] = fma2(hi2, cP[k], B[o]);
            }
        }
    }

    int jo = jo0 + tx;
    if (jo < M) {
        #pragma unroll
        for (int o = 0; o < 4; o++) {
            int io = io0 + 4 * ty + o;
            if (io < M) {
                float ll, lh, hl, hh;
                unpk(A[o], ll, lh);
                unpk(B[o], hl, hh);
                size_t off = (size_t)bc * M * OUTS + (size_t)io * OUTS + jo;
                outA[off] = ll;
                outM[off] = sqrtf(fmaf(lh, lh, fmaf(hl, hl, fmaf(hh, hh, EPSF))));
            }
        }
    }
}

// ---------------- 1-row DWT (tiny levels), f32x2 packed ----------------
__device__ __forceinline__ void dwt_one(const float* __restrict__ src,
                                        int N, int rstride, int roff,
                                        int jo, int io, float& outA, float& outM)
{
    const unsigned long long* cP =
        reinterpret_cast<const unsigned long long*>(c_Pf);
    int cb = 2 * jo - 6;
    int rb = 2 * io - 6;
    bool cint = (cb >= 0) && (cb + 7 < N);
    int ci[8];
    if (!cint) {
        #pragma unroll
        for (int k = 0; k < 8; k++) ci[k] = eidx(cb + k, N);
    }
    unsigned long long A = 0ull, B = 0ull;
    #pragma unroll
    for (int r = 0; r < 8; r++) {
        int ri = eidx(rb + r, N) - roff;
        const float* row = src + (size_t)ri * rstride;
        float lo, hi;
        if (cint) {
            const float2* q = reinterpret_cast<const float2*>(row + cb);
            unsigned long long acc = 0ull;
            #pragma unroll
            for (int h = 0; h < 4; h++) {
                float2 v = q[h];
                acc = fma2(bcast2(v.x), cP[2 * h],     acc);
                acc = fma2(bcast2(v.y), cP[2 * h + 1], acc);
            }
            unpk(acc, lo, hi);
        } else {
            lo = 0.f; hi = 0.f;
            #pragma unroll
            for (int k = 0; k < 8; k++) {
                float v = row[ci[k]];
                lo = fmaf(v, c_RL[k], lo);
                hi = fmaf(v, c_RH[k], hi);
            }
        }
        A = fma2(bcast2(lo), cP[r], A);
        B = fma2(bcast2(hi), cP[r], B);
    }
    float ll, lh, hl, hh;
    unpk(A, ll, lh);
    unpk(B, hl, hh);
    outA = ll;
    outM = sqrtf(fmaf(lh, lh, fmaf(hl, hl, fmaf(hh, hh, EPSF))));
}

// ---------------- merged levels 3+4, 8 partitions per bc (256 CTAs) ----------------
__global__ void __launch_bounds__(256)
tail_kernel(const float* __restrict__ cA2,
            float* __restrict__ m3, float* __restrict__ cA4, float* __restrict__ m4)
{
    __shared__ __align__(16) float sA3[16 * 72];   // window of cA3, stride 72
    int blk = blockIdx.x;          // 0..255
    int bc  = blk >> 3;
    int p   = blk & 7;
    int t   = threadIdx.x;
    const float* src2 = cA2 + (size_t)bc * M2 * S2;

    // owned level-4 rows: [5p, min(5p+5, 38))
    int l4lo = 5 * p;
    int l4hi = min(5 * p + 5, M4);
    // cA3 rows needed: e(t) for t in [2*l4lo-6, 2*(l4hi-1)+1]
    int tmin = 2 * l4lo - 6;
    int tmax = 2 * (l4hi - 1) + 1;
    int rlo = max(0, tmin);
    int rhi = min(M3 - 1, tmax);
    if (tmin < 0)        rhi = max(rhi, -1 - tmin);
    if (tmax > M3 - 1)   rlo = min(rlo, 2 * M3 - 1 - tmax);
    // owned m3 rows: [9p, min(9p+9, 70))
    int olo = 9 * p;
    int ohi = min(9 * p + 9, M3);
    rlo = min(rlo, olo);
    rhi = max(rhi, ohi - 1);
    int nr = rhi - rlo + 1;        // <= 16 by construction

    // Phase A: compute cA3 rows [rlo, rhi], write owned m3 rows
    for (int g = t; g < nr * 70; g += 256) {
        int jo = g % 70;
        int io = rlo + g / 70;
        float ll, mg;
        dwt_one(src2, M2, S2, 0, jo, io, ll, mg);
        sA3[(io - rlo) * 72 + jo] = ll;
        if (io >= olo && io < ohi)
            m3[(size_t)bc * M3 * S3 + io * S3 + jo] = mg;
    }
    __syncthreads();

    // Phase B: level 4 on smem window
    int nout = (l4hi - l4lo) * 38;     // <= 190, single pass
    if (t < nout) {
        int jo = t % 38;
        int io = l4lo + t / 38;
        float ll, mg;
        dwt_one(sA3, M3, 72, rlo, jo, io, ll, mg);
        size_t off = (size_t)bc * M4 * S4 + io * S4 + jo;
        cA4[off] = ll;
        m4[off]  = mg;
    }
}

// ---------------- upsample coordinates (jax.image.resize 'linear') ----------------
__device__ __forceinline__ void coord(int o, int n, int& i0, int& i1, float& f)
{
    float s  = (o + 0.5f) * (n * (1.0f / 512.0f)) - 0.5f;
    float fl = floorf(s);
    f = s - fl;
    int i = (int)fl;
    i0 = i < 0 ? 0 : i;
    int j = i + 1;
    i1 = j > n - 1 ? n - 1 : j;
}

// ---------------- fused separable upsample + merge + gate ----------------
// grid (32 y-blocks of 16 rows, 32 bc, 4 scales) = 4096 CTAs, block 256.
// Stage <=10 x-upsampled source rows in smem; y-interp warp-per-row with
// uniform coords and f32x2 math; gate folded into weights; streaming stores.
__global__ void __launch_bounds__(256, 8)
up_kernel(float* __restrict__ out,
          const float* __restrict__ t_emb, const float* __restrict__ gate_w)
{
    __shared__ __align__(16) float srow[11 * 512];   // 22 KB
    __shared__ float s_w;
    int ya  = blockIdx.x * 16;
    int bc  = blockIdx.y;
    int s   = blockIdx.z;
    int b   = bc >> 1, c = bc & 1;
    int tid = threadIdx.x;
    int wid = tid >> 5, lane = tid & 31;

    // gate: one warp, shuffle reduction over k=0..63
    if (tid < 32) {
        float acc = t_emb[b * 64 + tid]      * gate_w[tid * 4 + s]
                  + t_emb[b * 64 + tid + 32] * gate_w[(tid + 32) * 4 + s];
        #pragma unroll
        for (int o = 16; o; o >>= 1)
            acc += __shfl_xor_sync(0xffffffffu, acc, o);
        if (tid == 0)
            s_w = (s == 0 ? 0.5f : 1.0f) / (1.0f + expf(-acc));
    }

    int n, stride;
    const float* srcA;
    const float* srcB = 0;
    if      (s == 0) { n = M4; stride = S4; srcA = g_cA4 + (size_t)bc * M4 * S4;
                                            srcB = g_m4  + (size_t)bc * M4 * S4; }
    else if (s == 1) { n = M3; stride = S3; srcA = g_m3 + (size_t)bc * M3 * S3; }
    else if (s == 2) { n = M2; stride = S2; srcA = g_m2 + (size_t)bc * M2 * S2; }
    else             { n = M1; stride = S1; srcA = g_m1 + (size_t)bc * M1 * S1; }

    float rr = n * (1.0f / 512.0f);
    int i0a  = (int)floorf((ya + 0.5f)  * rr - 0.5f);
    int i1b  = (int)floorf((ya + 15.5f) * rr - 0.5f) + 1;
    int rloC = max(i0a, 0);
    int rhiC = min(i1b, n - 1);
    int nst  = rhiC - rloC + 1;    // <= 10

    // stage x-upsampled rows (raw, no gate)
    int xA0, xA1, xB0, xB1; float fA, fB;
    coord(tid,       n, xA0, xA1, fA);
    coord(tid + 256, n, xB0, xB1, fB);

    for (int r = 0; r < nst; r++) {
        const float* rowA = srcA + (size_t)(rloC + r) * stride;
        float a0 = rowA[xA0];
        float vA = a0 + (rowA[xA1] - a0) * fA;
        float b0 = rowA[xB0];
        float vB = b0 + (rowA[xB1] - b0) * fB;
        if (srcB) {
            const float* rowB = srcB + (size_t)(rloC + r) * stride;
            float c0 = rowB[xA0];
            vA += c0 + (rowB[xA1] - c0) * fA;
            float c1 = rowB[xB0];
            vB += c1 + (rowB[xB1] - c1) * fB;
        }
        srow[r * 512 + tid]       = vA;
        srow[r * 512 + tid + 256] = vB;
    }
    __syncthreads();

    // y-interp: warp-per-row (2 rows per warp), uniform coords, f32x2 math
    float w = s_w;
    size_t obase = ((size_t)(b * 8 + c * 4 + s)) * HW + (size_t)ya * 512;
    union F4 { float4 f; struct { unsigned long long lo, hi; } u; };
    #pragma unroll
    for (int j = 0; j < 2; j++) {
        int ry = wid * 2 + j;
        int y0, y1; float fy;
        coord(ya + ry, n, y0, y1, fy);
        float c1 = fy * w;
        float c0 = w - c1;
        unsigned long long c0_2 = bcast2(c0), c1_2 = bcast2(c1);
        const float4* r0 = reinterpret_cast<const float4*>(srow + (size_t)(y0 - rloC) * 512);
        const float4* r1 = reinterpret_cast<const float4*>(srow + (size_t)(y1 - rloC) * 512);
        float4* dst = reinterpret_cast<float4*>(out + obase + (size_t)ry * 512);
        #pragma unroll
        for (int it = 0; it < 4; it++) {
            int c4 = lane + it * 32;
            F4 a, d;
            a.f = r0[c4];
            d.f = r1[c4];
            unsigned long long v0 = fma2(a.u.lo, c0_2, mul2(d.u.lo, c1_2));
            unsigned long long v1 = fma2(a.u.hi, c0_2, mul2(d.u.hi, c1_2));
            st2_cs(dst + c4, v0, v1);
        }
    }
}

// ---------------- launch ----------------
extern "C" void kernel_launch(void* const* d_in, const int* in_sizes, int n_in,
                              void* d_out, int out_size)
{
    const float* image  = (const float*)d_in[0];
    const float* t_emb  = (const float*)d_in[1];
    const float* gate_w = (const float*)d_in[2];
    float* out = (float*)d_out;

    float *cA1, *m1, *cA2, *m2, *m3, *cA4, *m4;
    cudaGetSymbolAddress((void**)&cA1, g_cA1);
    cudaGetSymbolAddress((void**)&m1,  g_m1);
    cudaGetSymbolAddress((void**)&cA2, g_cA2);
    cudaGetSymbolAddress((void**)&m2,  g_m2);
    cudaGetSymbolAddress((void**)&m3,  g_m3);
    cudaGetSymbolAddress((void**)&cA4, g_cA4);
    cudaGetSymbolAddress((void**)&m4,  g_m4);

    dim3 blk(32, 8);
    {   dim3 g((M1 + 31) / 32, (M1 + 31) / 32, BC);   // 9 x 9 x 32
        dwt_tile_kernel<512, 512, M1, S1><<<g, blk>>>(image, cA1, m1); }
    {   dim3 g((M2 + 31) / 32, (M2 + 31) / 32, BC);   // 5 x 5 x 32
        dwt_tile_kernel<M1, S1, M2, S2><<<g, blk>>>(cA1, cA2, m2); }

    tail_kernel<<<BC * 8, 256>>>(cA2, m3, cA4, m4);

    up_kernel<<<dim3(32, BC, 4), 256>>>(out, t_emb, gate_w);
}